// round 13
// baseline (speedup 1.0000x reference)
#include <cuda_runtime.h>

// LinearInverse_45664092291621 — FINAL
//
// Reference analysis: score(x) = -x, and the function returns
// y + score(y) = y - y = 0 exactly, for every finite y. The 199-step
// Langevin scan, Threefry noise, and convergence logic are all dead code
// w.r.t. the output: the result is exactly zeros((1048576, 2), float32).
// The only mandatory work is writing the 8 MB output (poisoned before
// timing, so it must be written in full).
//
// Optimization search (all measured on the brokered Blackwell chip):
//   - STG zero-fill kernels, thin (2048 blk) / fat (512 blk) grids:
//       fill 4.7-4.8 us, totals 6.37-6.75 us
//   - TMA bulk-store (cp.async.bulk SMEM->GMEM): fill 5.09 us, total 6.85 us
//   - fork-join graph, 2 parallel memset nodes: total 8.22 us (regression)
//   - single driver memset node: 6.144-6.176 us, x4 reproductions
//     (spread = one 32 ns timer quantum)
// Every 8 MB fill pays ~the same fixed kernel overhead + the same
// L2-resident store traffic; the minimum-node graph (one memset node) is
// the floor. Alternate write paths and graph parallelism only add cost.
// The residual is one node's launch overhead + mandatory store traffic +
// the harness replay floor — none kernel-controllable.
//
// cudaMemsetAsync on the capture stream records a single graph memset node:
// graph-capturable, allocation-free, deterministic. Zeros are bytewise zero,
// so one byte-memset of the whole float32 buffer is exact for any out_size.

extern "C" void kernel_launch(void* const* d_in, const int* in_sizes, int n_in,
                              void* d_out, int out_size) {
    (void)d_in; (void)in_sizes; (void)n_in;
    cudaMemsetAsync(d_out, 0, (size_t)out_size * sizeof(float), 0);
}